// round 2
// baseline (speedup 1.0000x reference)
#include <cuda_runtime.h>

// Bilinear resample, 4 pixels per thread, branchless clamped gathers.
// imgs: (B,1024,1024,1) f32, dvfs: (B,1024,1024,2) f32, out: (B,1024,1024,1) f32.

#define HH 1024
#define WW 1024
#define HW (HH * WW)

struct Corner {
    const float* p00; const float* p01; const float* p10; const float* p11;
    float m00, m01, m10, m11;      // validity masks (0.0 / 1.0)
    float wx, wy;
};

__device__ __forceinline__ Corner setup_one(const float* __restrict__ img,
                                            int h, int w, float dx, float dy) {
    Corner c;
    float fx = (float)w + dx;
    float fy = (float)h + dy;
    float x0f = floorf(fx);
    float y0f = floorf(fy);
    c.wx = fx - x0f;
    c.wy = fy - y0f;
    int x0 = (int)x0f;
    int y0 = (int)y0f;
    int x1 = x0 + 1;
    int y1 = y0 + 1;

    float vx0 = (x0 >= 0 && x0 < WW) ? 1.0f : 0.0f;
    float vx1 = (x1 >= 0 && x1 < WW) ? 1.0f : 0.0f;
    float vy0 = (y0 >= 0 && y0 < HH) ? 1.0f : 0.0f;
    float vy1 = (y1 >= 0 && y1 < HH) ? 1.0f : 0.0f;

    int x0c = min(max(x0, 0), WW - 1);
    int x1c = min(max(x1, 0), WW - 1);
    int y0c = min(max(y0, 0), HH - 1);
    int y1c = min(max(y1, 0), HH - 1);

    const float* r0 = img + y0c * WW;
    const float* r1 = img + y1c * WW;
    c.p00 = r0 + x0c;  c.p01 = r0 + x1c;
    c.p10 = r1 + x0c;  c.p11 = r1 + x1c;
    c.m00 = vy0 * vx0; c.m01 = vy0 * vx1;
    c.m10 = vy1 * vx0; c.m11 = vy1 * vx1;
    return c;
}

__device__ __forceinline__ float combine(const Corner& c,
                                         float v00, float v01,
                                         float v10, float v11) {
    v00 *= c.m00; v01 *= c.m01; v10 *= c.m10; v11 *= c.m11;
    float omx = 1.0f - c.wx;
    float omy = 1.0f - c.wy;
    float top = v00 * omx + v01 * c.wx;
    float bot = v10 * omx + v11 * c.wx;
    return top * omy + bot * c.wy;
}

__global__ void __launch_bounds__(256)
bilinear_kernel(const float* __restrict__ imgs,
                const float* __restrict__ dvfs,
                float* __restrict__ out,
                int n_quads) {
    int t = blockIdx.x * blockDim.x + threadIdx.x;
    if (t >= n_quads) return;

    int idx = t * 4;                       // first pixel of the quad (row-aligned)
    int w = idx & (WW - 1);
    int h = (idx >> 10) & (HH - 1);
    int b = idx >> 20;

    const float* img = imgs + b * HW;

    // dvfs interleaved (x,y): 4 pixels -> 8 floats, streaming (touch-once)
    const float4* dv = reinterpret_cast<const float4*>(dvfs + (size_t)idx * 2);
    float4 d01 = __ldcs(dv);
    float4 d23 = __ldcs(dv + 1);

    // Phase 1: all address/weight setup (no loads yet)
    Corner c0 = setup_one(img, h, w,     d01.x, d01.y);
    Corner c1 = setup_one(img, h, w + 1, d01.z, d01.w);
    Corner c2 = setup_one(img, h, w + 2, d23.x, d23.y);
    Corner c3 = setup_one(img, h, w + 3, d23.z, d23.w);

    // Phase 2: issue all 16 independent gathers (max MLP)
    float a00 = __ldg(c0.p00), a01 = __ldg(c0.p01), a10 = __ldg(c0.p10), a11 = __ldg(c0.p11);
    float b00 = __ldg(c1.p00), b01 = __ldg(c1.p01), b10 = __ldg(c1.p10), b11 = __ldg(c1.p11);
    float e00 = __ldg(c2.p00), e01 = __ldg(c2.p01), e10 = __ldg(c2.p10), e11 = __ldg(c2.p11);
    float f00 = __ldg(c3.p00), f01 = __ldg(c3.p01), f10 = __ldg(c3.p10), f11 = __ldg(c3.p11);

    // Phase 3: combine
    float4 r;
    r.x = combine(c0, a00, a01, a10, a11);
    r.y = combine(c1, b00, b01, b10, b11);
    r.z = combine(c2, e00, e01, e10, e11);
    r.w = combine(c3, f00, f01, f10, f11);

    __stcs(reinterpret_cast<float4*>(out + idx), r);
}

extern "C" void kernel_launch(void* const* d_in, const int* in_sizes, int n_in,
                              void* d_out, int out_size) {
    const float* imgs = (const float*)d_in[0];
    const float* dvfs = (const float*)d_in[1];
    float* out = (float*)d_out;

    int total = out_size;          // B*H*W
    int n_quads = total / 4;
    int threads = 256;
    int blocks = (n_quads + threads - 1) / threads;
    bilinear_kernel<<<blocks, threads>>>(imgs, dvfs, out, n_quads);
}